// round 11
// baseline (speedup 1.0000x reference)
#include <cuda_runtime.h>

#define LAM 0.95f
#define ETA 0.5f
#define B_SZ 128
#define D_SZ 1024
#define VEC_PER_ROW (D_SZ / 4)   // 256
#define ROWS_PER_BLK 4

// out[b,i,j] = LAM*A[b,i,j] + ETA*h[b,i]*h[b,j]
//
// FINAL kernel — confirmed optimum (3x reproduced at 156.1 us):
//   - one block = 4 consecutive rows of one batch; 256 threads; thread t owns
//     column-group j4 = t for all 4 rows (hj loaded once; h is L2-resident)
//   - 4 A loads front-batched (MLP=4), evict-first (.cs) on both streams
//   - 2D grid (256 row-groups x 128 batches) = 32768 blocks, occ ~81%, regs 32
// Measured: 6.86 TB/s sustained (86.5% DRAM) — HBM read/write-turnaround
// bound. Neutral/worse: MLP=8, 2x4 grouping, st.wt, default-cached loads,
// 256-bit v8 accesses, 128-thread blocks.
__global__ void __launch_bounds__(256) fastweight_kernel(
    const float4* __restrict__ A,
    const float* __restrict__ h,
    float4* __restrict__ out)
{
    int b  = blockIdx.y;
    int i0 = blockIdx.x * ROWS_PER_BLK;
    int t  = threadIdx.x;                 // j4 in [0,256)

    int base = (b * D_SZ + i0) * VEC_PER_ROW + t;   // fits in 32 bits

    const float4 hj = __ldg(((const float4*)h) + b * VEC_PER_ROW + t);

    const float* hrow = h + b * D_SZ + i0;
    float hi0 = __ldg(hrow + 0) * ETA;
    float hi1 = __ldg(hrow + 1) * ETA;
    float hi2 = __ldg(hrow + 2) * ETA;
    float hi3 = __ldg(hrow + 3) * ETA;

    // Front-batch the 4 streaming loads (MLP=4)
    float4 a0 = __ldcs(A + base + 0 * VEC_PER_ROW);
    float4 a1 = __ldcs(A + base + 1 * VEC_PER_ROW);
    float4 a2 = __ldcs(A + base + 2 * VEC_PER_ROW);
    float4 a3 = __ldcs(A + base + 3 * VEC_PER_ROW);

    float4 r;
    r.x = fmaf(hi0, hj.x, a0.x * LAM);
    r.y = fmaf(hi0, hj.y, a0.y * LAM);
    r.z = fmaf(hi0, hj.z, a0.z * LAM);
    r.w = fmaf(hi0, hj.w, a0.w * LAM);
    __stcs(out + base + 0 * VEC_PER_ROW, r);

    r.x = fmaf(hi1, hj.x, a1.x * LAM);
    r.y = fmaf(hi1, hj.y, a1.y * LAM);
    r.z = fmaf(hi1, hj.z, a1.z * LAM);
    r.w = fmaf(hi1, hj.w, a1.w * LAM);
    __stcs(out + base + 1 * VEC_PER_ROW, r);

    r.x = fmaf(hi2, hj.x, a2.x * LAM);
    r.y = fmaf(hi2, hj.y, a2.y * LAM);
    r.z = fmaf(hi2, hj.z, a2.z * LAM);
    r.w = fmaf(hi2, hj.w, a2.w * LAM);
    __stcs(out + base + 2 * VEC_PER_ROW, r);

    r.x = fmaf(hi3, hj.x, a3.x * LAM);
    r.y = fmaf(hi3, hj.y, a3.y * LAM);
    r.z = fmaf(hi3, hj.z, a3.z * LAM);
    r.w = fmaf(hi3, hj.w, a3.w * LAM);
    __stcs(out + base + 3 * VEC_PER_ROW, r);
}

extern "C" void kernel_launch(void* const* d_in, const int* in_sizes, int n_in,
                              void* d_out, int out_size) {
    const float4* A = (const float4*)d_in[0];
    const float*  h = (const float*)d_in[1];
    float4* out = (float4*)d_out;

    dim3 grid(D_SZ / ROWS_PER_BLK, B_SZ);   // (256, 128) = 32768 blocks
    fastweight_kernel<<<grid, 256>>>(A, h, out);
}

// round 12
// speedup vs baseline: 1.0059x; 1.0059x over previous
#include <cuda_runtime.h>

#define LAM 0.95f
#define ETA 0.5f
#define B_SZ 128
#define D_SZ 1024
#define VEC_PER_ROW (D_SZ / 4)   // 256
#define ROWS_PER_BLK 4

// out[b,i,j] = LAM*A[b,i,j] + ETA*h[b,i]*h[b,j]
//
// FINAL kernel — best + most reproducible configuration (156.128 us wall,
// measured identically in two separate rounds; DRAM 86.5%, 6.86 TB/s):
//   - one block = 4 consecutive rows of one batch; 256 threads; thread t owns
//     column-group j4 = t for all 4 rows (hj loaded once; h is L2-resident)
//   - 4 A loads front-batched (MLP=4), evict-first (.cs) on both streams
//   - 1D grid of 32768 independent blocks, occ ~81%, regs 32
// HBM read/write-turnaround bound: issue=10%, fma=6%, alu=2.5%. Tested and
// neutral/worse: MLP=8, 2x4 row grouping, st.wt, default-cached loads,
// 256-bit v8 accesses, 128-thread blocks, 2D grid.
__global__ void __launch_bounds__(256) fastweight_kernel(
    const float4* __restrict__ A,
    const float* __restrict__ h,
    float4* __restrict__ out)
{
    int blk = blockIdx.x;
    int b  = blk >> 8;                    // 256 row-groups per batch (1024/4)
    int rg = blk & 255;
    int i0 = rg * ROWS_PER_BLK;
    int t  = threadIdx.x;                 // j4 in [0,256)

    int base = (b * D_SZ + i0) * VEC_PER_ROW + t;   // fits in 32 bits

    const float4 hj = __ldg(((const float4*)h) + b * VEC_PER_ROW + t);

    const float* hrow = h + b * D_SZ + i0;
    float hi0 = __ldg(hrow + 0) * ETA;
    float hi1 = __ldg(hrow + 1) * ETA;
    float hi2 = __ldg(hrow + 2) * ETA;
    float hi3 = __ldg(hrow + 3) * ETA;

    // Front-batch the 4 streaming loads (MLP=4)
    float4 a0 = __ldcs(A + base + 0 * VEC_PER_ROW);
    float4 a1 = __ldcs(A + base + 1 * VEC_PER_ROW);
    float4 a2 = __ldcs(A + base + 2 * VEC_PER_ROW);
    float4 a3 = __ldcs(A + base + 3 * VEC_PER_ROW);

    float4 r;
    r.x = fmaf(hi0, hj.x, a0.x * LAM);
    r.y = fmaf(hi0, hj.y, a0.y * LAM);
    r.z = fmaf(hi0, hj.z, a0.z * LAM);
    r.w = fmaf(hi0, hj.w, a0.w * LAM);
    __stcs(out + base + 0 * VEC_PER_ROW, r);

    r.x = fmaf(hi1, hj.x, a1.x * LAM);
    r.y = fmaf(hi1, hj.y, a1.y * LAM);
    r.z = fmaf(hi1, hj.z, a1.z * LAM);
    r.w = fmaf(hi1, hj.w, a1.w * LAM);
    __stcs(out + base + 1 * VEC_PER_ROW, r);

    r.x = fmaf(hi2, hj.x, a2.x * LAM);
    r.y = fmaf(hi2, hj.y, a2.y * LAM);
    r.z = fmaf(hi2, hj.z, a2.z * LAM);
    r.w = fmaf(hi2, hj.w, a2.w * LAM);
    __stcs(out + base + 2 * VEC_PER_ROW, r);

    r.x = fmaf(hi3, hj.x, a3.x * LAM);
    r.y = fmaf(hi3, hj.y, a3.y * LAM);
    r.z = fmaf(hi3, hj.z, a3.z * LAM);
    r.w = fmaf(hi3, hj.w, a3.w * LAM);
    __stcs(out + base + 3 * VEC_PER_ROW, r);
}

extern "C" void kernel_launch(void* const* d_in, const int* in_sizes, int n_in,
                              void* d_out, int out_size) {
    const float4* A = (const float4*)d_in[0];
    const float*  h = (const float*)d_in[1];
    float4* out = (float4*)d_out;

    // grid = B * (D / 4) = 128 * 256 = 32768 blocks
    int blocks = B_SZ * (D_SZ / ROWS_PER_BLK);
    fastweight_kernel<<<blocks, 256>>>(A, h, out);
}

// round 13
// speedup vs baseline: 1.0064x; 1.0004x over previous
#include <cuda_runtime.h>

#define LAM 0.95f
#define ETA 0.5f
#define B_SZ 128
#define D_SZ 1024
#define VEC_PER_ROW (D_SZ / 4)   // 256
#define ROWS_PER_BLK 4

// out[b,i,j] = LAM*A[b,i,j] + ETA*h[b,i]*h[b,j]
//
// Converged configuration (156.1 us, DRAM ~86%, 6.86 TB/s) with one final
// micro-variation: compute all 4 results in-place (a[] overwritten, regs
// stay 32), then issue the 4 STG.128 back-to-back — batched write phase per
// warp to present longer same-direction runs to the HBM scheduler
// (read/write turnaround is the binding constraint).
__global__ void __launch_bounds__(256) fastweight_kernel(
    const float4* __restrict__ A,
    const float* __restrict__ h,
    float4* __restrict__ out)
{
    int blk = blockIdx.x;
    int b  = blk >> 8;                    // 256 row-groups per batch (1024/4)
    int rg = blk & 255;
    int i0 = rg * ROWS_PER_BLK;
    int t  = threadIdx.x;                 // j4 in [0,256)

    int base = (b * D_SZ + i0) * VEC_PER_ROW + t;   // fits in 32 bits

    const float4 hj = __ldg(((const float4*)h) + b * VEC_PER_ROW + t);

    const float* hrow = h + b * D_SZ + i0;
    float hi0 = __ldg(hrow + 0) * ETA;
    float hi1 = __ldg(hrow + 1) * ETA;
    float hi2 = __ldg(hrow + 2) * ETA;
    float hi3 = __ldg(hrow + 3) * ETA;

    // Read phase: 4 front-batched streaming loads (MLP=4)
    float4 a0 = __ldcs(A + base + 0 * VEC_PER_ROW);
    float4 a1 = __ldcs(A + base + 1 * VEC_PER_ROW);
    float4 a2 = __ldcs(A + base + 2 * VEC_PER_ROW);
    float4 a3 = __ldcs(A + base + 3 * VEC_PER_ROW);

    // Compute phase: results in place, registers stay at 32
    a0.x = fmaf(hi0, hj.x, a0.x * LAM);
    a0.y = fmaf(hi0, hj.y, a0.y * LAM);
    a0.z = fmaf(hi0, hj.z, a0.z * LAM);
    a0.w = fmaf(hi0, hj.w, a0.w * LAM);

    a1.x = fmaf(hi1, hj.x, a1.x * LAM);
    a1.y = fmaf(hi1, hj.y, a1.y * LAM);
    a1.z = fmaf(hi1, hj.z, a1.z * LAM);
    a1.w = fmaf(hi1, hj.w, a1.w * LAM);

    a2.x = fmaf(hi2, hj.x, a2.x * LAM);
    a2.y = fmaf(hi2, hj.y, a2.y * LAM);
    a2.z = fmaf(hi2, hj.z, a2.z * LAM);
    a2.w = fmaf(hi2, hj.w, a2.w * LAM);

    a3.x = fmaf(hi3, hj.x, a3.x * LAM);
    a3.y = fmaf(hi3, hj.y, a3.y * LAM);
    a3.z = fmaf(hi3, hj.z, a3.z * LAM);
    a3.w = fmaf(hi3, hj.w, a3.w * LAM);

    // Write phase: 4 back-to-back streaming stores
    __stcs(out + base + 0 * VEC_PER_ROW, a0);
    __stcs(out + base + 1 * VEC_PER_ROW, a1);
    __stcs(out + base + 2 * VEC_PER_ROW, a2);
    __stcs(out + base + 3 * VEC_PER_ROW, a3);
}

extern "C" void kernel_launch(void* const* d_in, const int* in_sizes, int n_in,
                              void* d_out, int out_size) {
    const float4* A = (const float4*)d_in[0];
    const float*  h = (const float*)d_in[1];
    float4* out = (float4*)d_out;

    // grid = B * (D / 4) = 128 * 256 = 32768 blocks
    int blocks = B_SZ * (D_SZ / ROWS_PER_BLK);
    fastweight_kernel<<<blocks, 256>>>(A, h, out);
}